// round 2
// baseline (speedup 1.0000x reference)
#include <cuda_runtime.h>

#define BB     128      // batch
#define NNODE  512      // nodes
#define FIN_   2
#define COUT_  64
#define CIN_   66       // FIN + COUT
#define BF     8448     // BB * CIN_
#define KMLP   462      // 7 * CIN_

// ---------------- scratch (static device globals; no runtime allocation) ----
static __device__ float g_ADP[2][NNODE * NNODE];       // adp1, adp2 (natural [n][m])
static __device__ float g_X  [NNODE * BF];             // packed X  [n][b*66+f]
static __device__ float g_X1 [3][NNODE * BF];          // 1st-order diffusion per support
static __device__ float g_X2 [3][NNODE * BF];          // 2nd-order diffusion per support
static __device__ float g_V  [NNODE * BB * 128];       // gate output (r | u), row = n*128+b

// ---------------- packed f32x2 helpers (FFMA2: 2x fp32 throughput) ----------
__device__ __forceinline__ void ffma2(unsigned long long &d, unsigned long long a,
                                      unsigned long long b) {
    asm("fma.rn.f32x2 %0, %1, %2, %0;" : "+l"(d) : "l"(a), "l"(b));
}
__device__ __forceinline__ unsigned long long bcast2(float x) {
    unsigned long long r;
    asm("mov.b64 %0, {%1, %1};" : "=l"(r) : "f"(x));
    return r;
}
__device__ __forceinline__ float2 unpk2(unsigned long long v) {
    float lo, hi;
    asm("mov.b64 {%0, %1}, %2;" : "=f"(lo), "=f"(hi) : "l"(v));
    return make_float2(lo, hi);
}

// ---------------- adaptive adjacency: softmax(relu(nv1@nv2), axis=1) --------
// one block per (row n, which); 512 threads = one per column m
__global__ void k_adp(const float* __restrict__ nv1a, const float* __restrict__ nv2a,
                      const float* __restrict__ nv1b, const float* __restrict__ nv2b) {
    const int which = blockIdx.y;
    const float* nv1 = which ? nv1b : nv1a;
    const float* nv2 = which ? nv2b : nv2a;
    const int n = blockIdx.x;
    const int m = threadIdx.x;

    float w[10];
#pragma unroll
    for (int t = 0; t < 10; t++) w[t] = nv1[n * 10 + t];
    float v = 0.f;
#pragma unroll
    for (int t = 0; t < 10; t++) v += w[t] * nv2[t * NNODE + m];
    v = fmaxf(v, 0.f);

    __shared__ float red[512];
    red[m] = v;
    __syncthreads();
    for (int s = 256; s > 0; s >>= 1) {
        if (m < s) red[m] = fmaxf(red[m], red[m + s]);
        __syncthreads();
    }
    float mx = red[0];
    __syncthreads();
    float e = __expf(v - mx);
    red[m] = e;
    __syncthreads();
    for (int s = 256; s > 0; s >>= 1) {
        if (m < s) red[m] += red[m + s];
        __syncthreads();
    }
    g_ADP[which][n * NNODE + m] = e / red[0];
}

// ---------------- pack kernels ----------------------------------------------
__global__ void k_pack1(const float* __restrict__ inp, const float* __restrict__ st) {
    int idx = blockIdx.x * 256 + threadIdx.x;
    if (idx >= NNODE * BF) return;
    int n = idx / BF;
    int r = idx - n * BF;
    int b = r / CIN_;
    int f = r - b * CIN_;
    float v = (f < FIN_) ? inp[(b * NNODE + n) * FIN_ + f]
                         : st[(b * NNODE + n) * COUT_ + (f - FIN_)];
    g_X[idx] = v;
}

__global__ void k_pack2(const float* __restrict__ inp, const float* __restrict__ st) {
    int idx = blockIdx.x * 256 + threadIdx.x;
    if (idx >= NNODE * BF) return;
    int n = idx / BF;
    int r = idx - n * BF;
    int b = r / CIN_;
    int f = r - b * CIN_;
    float v;
    if (f < FIN_) {
        v = inp[(b * NNODE + n) * FIN_ + f];
    } else {
        int c = f - FIN_;
        float rr = g_V[(n * BB + b) * 128 + c];      // r gate
        v = rr * st[(b * NNODE + n) * COUT_ + c];
    }
    g_X[idx] = v;
}

// ---------------- diffusion GEMM (TN): C[m][j] = sum_n A[n][m] * B[n][j] ----
// M=512, K=512, Ncols=8448. BM=BN=128, BK=16, 256 threads, 8x8 micro (f32x2),
// double-buffered smem. grid = (66, 4, 3supports)
__global__ void __launch_bounds__(256, 2)
k_diff(const float* __restrict__ A0, const float* __restrict__ A1,
       int adpWhich, int stage) {
    const int z = blockIdx.z;
    const float* __restrict__ A = (z == 0) ? A0 : (z == 1) ? A1 : g_ADP[adpWhich];
    const float* __restrict__ B = (stage == 0) ? g_X : g_X1[z];
    float* __restrict__ C = (stage == 0) ? g_X1[z] : g_X2[z];

    __shared__ __align__(16) float As[2][16][128];
    __shared__ __align__(16) float Bs[2][16][128];

    const int tid = threadIdx.x;
    const int m0 = blockIdx.y * 128;
    const int j0 = blockIdx.x * 128;
    const int tx = tid & 15, ty = tid >> 4;
    const int mm = ty * 8, jj = tx * 8;
    const int lr = tid >> 5;          // 0..7
    const int lc = (tid & 31) * 4;    // 0..124

    unsigned long long acc[8][4];
#pragma unroll
    for (int i = 0; i < 8; i++)
#pragma unroll
        for (int j = 0; j < 4; j++) acc[i][j] = 0ULL;

    float4 ra0, ra1, rb0, rb1;
    // prologue: tile 0
    ra0 = *(const float4*)(A + (lr) * 512 + m0 + lc);
    ra1 = *(const float4*)(A + (8 + lr) * 512 + m0 + lc);
    rb0 = *(const float4*)(B + (lr) * BF + j0 + lc);
    rb1 = *(const float4*)(B + (8 + lr) * BF + j0 + lc);
    *(float4*)&As[0][lr][lc] = ra0;
    *(float4*)&As[0][8 + lr][lc] = ra1;
    *(float4*)&Bs[0][lr][lc] = rb0;
    *(float4*)&Bs[0][8 + lr][lc] = rb1;
    __syncthreads();

    int buf = 0;
    for (int t = 0; t < 32; t++) {
        if (t < 31) {
            const int k0 = (t + 1) * 16;
            ra0 = *(const float4*)(A + (k0 + lr) * 512 + m0 + lc);
            ra1 = *(const float4*)(A + (k0 + 8 + lr) * 512 + m0 + lc);
            rb0 = *(const float4*)(B + (k0 + lr) * BF + j0 + lc);
            rb1 = *(const float4*)(B + (k0 + 8 + lr) * BF + j0 + lc);
        }
#pragma unroll
        for (int kk = 0; kk < 16; kk++) {
            const unsigned long long* bp =
                (const unsigned long long*)&Bs[buf][kk][jj];
            unsigned long long bv0 = bp[0], bv1 = bp[1], bv2 = bp[2], bv3 = bp[3];
#pragma unroll
            for (int i = 0; i < 8; i++) {
                unsigned long long av = bcast2(As[buf][kk][mm + i]);
                ffma2(acc[i][0], av, bv0);
                ffma2(acc[i][1], av, bv1);
                ffma2(acc[i][2], av, bv2);
                ffma2(acc[i][3], av, bv3);
            }
        }
        if (t < 31) {
            const int nb = buf ^ 1;
            *(float4*)&As[nb][lr][lc] = ra0;
            *(float4*)&As[nb][8 + lr][lc] = ra1;
            *(float4*)&Bs[nb][lr][lc] = rb0;
            *(float4*)&Bs[nb][8 + lr][lc] = rb1;
            __syncthreads();
            buf = nb;
        }
    }

#pragma unroll
    for (int i = 0; i < 8; i++) {
        float2* cp = (float2*)(C + (m0 + mm + i) * BF + j0 + jj);
#pragma unroll
        for (int j = 0; j < 4; j++) cp[j] = unpk2(acc[i][j]);
    }
}

// ---------------- output GEMM: [65536 x 462] @ [462 x BN] + fused epilogue --
// Rows r = n*128+b gather K=462 from 7 chunk buffers (33-wide K tiles stay in
// one chunk). ACT 0: sigmoid -> g_V ; ACT 1: tanh + GRU combine -> out.
template <int BN, int ACT>
__global__ void __launch_bounds__(256)
k_out(const float* __restrict__ W, const float* __restrict__ bias,
      const float* __restrict__ state, float* __restrict__ outp) {
    constexpr int TN = BN / 16;   // 8 or 4 cols per thread
    constexpr int TN2 = TN / 2;
    __shared__ __align__(16) float Hs[128 * 33];
    __shared__ __align__(16) float Ws[33 * BN];

    const int tid = threadIdx.x;
    const int row0 = blockIdx.x * 128;
    const int tx = tid & 15, ty = tid >> 4;
    const int mm = ty * 8, cc0 = tx * TN;

    unsigned long long acc[8][TN2];
#pragma unroll
    for (int i = 0; i < 8; i++)
#pragma unroll
        for (int j = 0; j < TN2; j++) acc[i][j] = 0ULL;

    const float* chunks[7] = {g_X,     g_X1[0], g_X2[0], g_X1[1],
                              g_X2[1], g_X1[2], g_X2[2]};

    for (int kt = 0; kt < 14; kt++) {
        const int t = kt >> 1;
        const int fb = (kt & 1) * 33;
        const float* __restrict__ Hc = chunks[t];
        for (int i = tid; i < 128 * 33; i += 256) {
            int r = i / 33, f = i - r * 33;
            Hs[i] = Hc[(row0 + r) * CIN_ + fb + f];
        }
        for (int i = tid; i < 33 * BN; i += 256) {
            int kk = i / BN, c = i - kk * BN;
            Ws[i] = W[(t * CIN_ + fb + kk) * BN + c];
        }
        __syncthreads();
#pragma unroll 3
        for (int kk = 0; kk < 33; kk++) {
            const unsigned long long* bp =
                (const unsigned long long*)&Ws[kk * BN + cc0];
            unsigned long long bv[TN2];
#pragma unroll
            for (int j = 0; j < TN2; j++) bv[j] = bp[j];
#pragma unroll
            for (int i = 0; i < 8; i++) {
                unsigned long long av = bcast2(Hs[(mm + i) * 33 + kk]);
#pragma unroll
                for (int j = 0; j < TN2; j++) ffma2(acc[i][j], av, bv[j]);
            }
        }
        __syncthreads();
    }

#pragma unroll
    for (int i = 0; i < 8; i++) {
        const int row = row0 + mm + i;
#pragma unroll
        for (int j = 0; j < TN2; j++) {
            float2 v = unpk2(acc[i][j]);
            const int c = cc0 + 2 * j;
            if (ACT == 0) {
                float s0 = 1.f / (1.f + __expf(-(v.x + bias[c])));
                float s1 = 1.f / (1.f + __expf(-(v.y + bias[c + 1])));
                g_V[row * 128 + c] = s0;
                g_V[row * 128 + c + 1] = s1;
            } else {
                const int n = row >> 7, b = row & 127;
                float c0 = tanhf(v.x + bias[c]);
                float c1 = tanhf(v.y + bias[c + 1]);
                float u0 = g_V[row * 128 + 64 + c];
                float u1 = g_V[row * 128 + 64 + c + 1];
                const int si = (b * NNODE + n) * COUT_ + c;
                float st0 = state[si], st1 = state[si + 1];
                outp[si]     = u0 * st0 + (1.f - u0) * c0;
                outp[si + 1] = u1 * st1 + (1.f - u1) * c1;
            }
        }
    }
}

// ---------------- launch ----------------------------------------------------
extern "C" void kernel_launch(void* const* d_in, const int* in_sizes, int n_in,
                              void* d_out, int out_size) {
    const float* input = (const float*)d_in[0];
    const float* state = (const float*)d_in[1];
    const float* A0    = (const float*)d_in[2];
    const float* A1    = (const float*)d_in[3];
    const float* nv1_1 = (const float*)d_in[4];
    const float* nv2_1 = (const float*)d_in[5];
    const float* W1    = (const float*)d_in[6];
    const float* b1    = (const float*)d_in[7];
    const float* nv1_2 = (const float*)d_in[8];
    const float* nv2_2 = (const float*)d_in[9];
    const float* W2    = (const float*)d_in[10];
    const float* b2    = (const float*)d_in[11];
    float* outp = (float*)d_out;

    const int packGrid = (NNODE * BF + 255) / 256;
    const dim3 gd(BF / 128, NNODE / 128, 3);   // (66, 4, 3)

    k_adp<<<dim3(NNODE, 2), 512>>>(nv1_1, nv2_1, nv1_2, nv2_2);
    k_pack1<<<packGrid, 256>>>(input, state);

    // GCN 1
    k_diff<<<gd, 256>>>(A0, A1, /*adp*/0, /*stage*/0);
    k_diff<<<gd, 256>>>(A0, A1, 0, 1);
    k_out<128, 0><<<NNODE * BB / 128, 256>>>(W1, b1, state, nullptr);

    // GCN 2
    k_pack2<<<packGrid, 256>>>(input, state);
    k_diff<<<gd, 256>>>(A0, A1, 1, 0);
    k_diff<<<gd, 256>>>(A0, A1, 1, 1);
    k_out<64, 1><<<NNODE * BB / 128, 256>>>(W2, b2, state, outp);
}

// round 7
// speedup vs baseline: 1.6215x; 1.6215x over previous
#include <cuda_runtime.h>
#include <cuda_bf16.h>
#include <cstdint>

#define BB     128
#define NNODE  512
#define FIN_   2
#define COUT_  64
#define CIN_   66
#define BF     8448     // BB * CIN_

// ---------------- scratch (static device globals) ---------------------------
static __device__ float g_ADP[2][NNODE * NNODE];
static __device__ float g_X  [NNODE * BF];
static __device__ float g_X1 [3][NNODE * BF];
static __device__ float g_X2 [3][NNODE * BF];
static __device__ float g_V  [NNODE * BB * 128];
static __device__ __nv_bfloat16 g_ATh[4][NNODE * NNODE];   // A0,A1,adp1,adp2 transposed, hi
static __device__ __nv_bfloat16 g_ATl[4][NNODE * NNODE];   // lo
static __device__ __nv_bfloat16 g_XTh[BF * NNODE];         // X^T hi  [j][n]
static __device__ __nv_bfloat16 g_XTl[BF * NNODE];
static __device__ __nv_bfloat16 g_X1Th[3][BF * NNODE];     // X1^T hi per support
static __device__ __nv_bfloat16 g_X1Tl[3][BF * NNODE];

// ---------------- PTX helpers -----------------------------------------------
__device__ __forceinline__ uint32_t smem_u32(const void* p) {
    uint32_t a;
    asm("{ .reg .u64 t; cvta.to.shared.u64 t, %1; cvt.u32.u64 %0, t; }" : "=r"(a) : "l"(p));
    return a;
}
#define SWZ128(off) ((off) ^ (((off) >> 3) & 0x70))

#define CP_ASYNC16(sm, gp) \
    asm volatile("cp.async.cg.shared.global [%0], [%1], 16;" :: "r"(sm), "l"(gp))
#define CP_COMMIT() asm volatile("cp.async.commit_group;" ::: "memory")
#define CP_WAIT(n)  asm volatile("cp.async.wait_group %0;" :: "n"(n) : "memory")

__device__ __forceinline__ void ldsm_x4(uint32_t* r, uint32_t addr) {
    asm volatile("ldmatrix.sync.aligned.m8n8.x4.shared.b16 {%0,%1,%2,%3}, [%4];"
                 : "=r"(r[0]), "=r"(r[1]), "=r"(r[2]), "=r"(r[3]) : "r"(addr));
}
__device__ __forceinline__ void ldsm_x2(uint32_t* r, uint32_t addr) {
    asm volatile("ldmatrix.sync.aligned.m8n8.x2.shared.b16 {%0,%1}, [%2];"
                 : "=r"(r[0]), "=r"(r[1]) : "r"(addr));
}
__device__ __forceinline__ void mma16816(float* c, const uint32_t* a, const uint32_t* b) {
    asm volatile("mma.sync.aligned.m16n8k16.row.col.f32.bf16.bf16.f32 "
                 "{%0,%1,%2,%3}, {%4,%5,%6,%7}, {%8,%9}, {%0,%1,%2,%3};"
                 : "+f"(c[0]), "+f"(c[1]), "+f"(c[2]), "+f"(c[3])
                 : "r"(a[0]), "r"(a[1]), "r"(a[2]), "r"(a[3]), "r"(b[0]), "r"(b[1]));
}

// ---------------- FFMA2 helpers (k_out) -------------------------------------
__device__ __forceinline__ void ffma2(unsigned long long &d, unsigned long long a,
                                      unsigned long long b) {
    asm("fma.rn.f32x2 %0, %1, %2, %0;" : "+l"(d) : "l"(a), "l"(b));
}
__device__ __forceinline__ unsigned long long bcast2(float x) {
    unsigned long long r;
    asm("mov.b64 %0, {%1, %1};" : "=l"(r) : "f"(x));
    return r;
}
__device__ __forceinline__ float2 unpk2(unsigned long long v) {
    float lo, hi;
    asm("mov.b64 {%0, %1}, %2;" : "=f"(lo), "=f"(hi) : "l"(v));
    return make_float2(lo, hi);
}

// ---------------- adaptive adjacency ----------------------------------------
__global__ void k_adp(const float* __restrict__ nv1a, const float* __restrict__ nv2a,
                      const float* __restrict__ nv1b, const float* __restrict__ nv2b) {
    const int which = blockIdx.y;
    const float* nv1 = which ? nv1b : nv1a;
    const float* nv2 = which ? nv2b : nv2a;
    const int n = blockIdx.x, m = threadIdx.x;
    float w[10];
#pragma unroll
    for (int t = 0; t < 10; t++) w[t] = nv1[n * 10 + t];
    float v = 0.f;
#pragma unroll
    for (int t = 0; t < 10; t++) v += w[t] * nv2[t * NNODE + m];
    v = fmaxf(v, 0.f);
    __shared__ float red[512];
    red[m] = v; __syncthreads();
    for (int s = 256; s > 0; s >>= 1) { if (m < s) red[m] = fmaxf(red[m], red[m + s]); __syncthreads(); }
    float mx = red[0]; __syncthreads();
    float e = __expf(v - mx);
    red[m] = e; __syncthreads();
    for (int s = 256; s > 0; s >>= 1) { if (m < s) red[m] += red[m + s]; __syncthreads(); }
    g_ADP[which][n * NNODE + m] = e / red[0];
}

// ---------------- A transpose + bf16 split ----------------------------------
__global__ void k_prepA(const float* __restrict__ A0, const float* __restrict__ A1) {
    const int a = blockIdx.z;
    const float* __restrict__ src = (a == 0) ? A0 : (a == 1) ? A1 : g_ADP[a - 2];
    __shared__ float t[32][33];
    const int mb = blockIdx.x * 32, nb = blockIdx.y * 32;
    const int tx = threadIdx.x & 31, ty = threadIdx.x >> 5;
#pragma unroll
    for (int r = 0; r < 32; r += 8)
        t[ty + r][tx] = src[(nb + ty + r) * NNODE + mb + tx];
    __syncthreads();
#pragma unroll
    for (int r = 0; r < 32; r += 8) {
        float v = t[tx][ty + r];                       // A[nb+tx][mb+ty+r]
        __nv_bfloat16 h = __float2bfloat16(v);
        float rem = v - __bfloat162float(h);
        int o = (mb + ty + r) * NNODE + nb + tx;       // AT[m][n]
        g_ATh[a][o] = h;
        g_ATl[a][o] = __float2bfloat16(rem);
    }
}

// ---------------- X transpose + bf16 split ----------------------------------
__global__ void k_split(int mode) {
    const int z = (mode == 0) ? -1 : (int)blockIdx.z;
    const float* __restrict__ src = (z < 0) ? g_X : g_X1[z];
    __nv_bfloat16* __restrict__ dh = (z < 0) ? g_XTh : g_X1Th[z];
    __nv_bfloat16* __restrict__ dl = (z < 0) ? g_XTl : g_X1Tl[z];
    __shared__ float t[32][33];
    const int jb = blockIdx.x * 32, nb = blockIdx.y * 32;
    const int tx = threadIdx.x & 31, ty = threadIdx.x >> 5;
#pragma unroll
    for (int r = 0; r < 32; r += 8)
        t[ty + r][tx] = src[(size_t)(nb + ty + r) * BF + jb + tx];
    __syncthreads();
#pragma unroll
    for (int r = 0; r < 32; r += 8) {
        float v = t[tx][ty + r];                       // X[nb+tx][jb+ty+r]
        __nv_bfloat16 h = __float2bfloat16(v);
        float rem = v - __bfloat162float(h);
        size_t o = (size_t)(jb + ty + r) * NNODE + nb + tx;   // XT[j][n]
        dh[o] = h;
        dl[o] = __float2bfloat16(rem);
    }
}

// ---------------- pack kernels ----------------------------------------------
__global__ void k_pack1(const float* __restrict__ inp, const float* __restrict__ st) {
    int idx = blockIdx.x * 256 + threadIdx.x;
    if (idx >= NNODE * BF) return;
    int n = idx / BF, r = idx - n * BF;
    int b = r / CIN_, f = r - b * CIN_;
    g_X[idx] = (f < FIN_) ? inp[(b * NNODE + n) * FIN_ + f]
                          : st[(b * NNODE + n) * COUT_ + (f - FIN_)];
}
__global__ void k_pack2(const float* __restrict__ inp, const float* __restrict__ st) {
    int idx = blockIdx.x * 256 + threadIdx.x;
    if (idx >= NNODE * BF) return;
    int n = idx / BF, r = idx - n * BF;
    int b = r / CIN_, f = r - b * CIN_;
    float v;
    if (f < FIN_) v = inp[(b * NNODE + n) * FIN_ + f];
    else {
        int c = f - FIN_;
        v = g_V[(n * BB + b) * 128 + c] * st[(b * NNODE + n) * COUT_ + c];
    }
    g_X[idx] = v;
}

// ---------------- diffusion GEMM on HMMA (mma.sync, split-bf16 x3) ----------
// C[m][j] = sum_n AT[m][n] * XT[j][n];  BM=128, BN=128, BK=64, K=512
#define OFF_AH 0
#define OFF_AL 16384
#define OFF_BH 32768
#define OFF_BL 49152
#define BUFSZ  65536
#define DIFF_SMEM (2 * BUFSZ)   // 131072

__device__ __forceinline__ void diff_load(uint32_t sb, int buf,
                                          const __nv_bfloat16* Ah, const __nv_bfloat16* Al,
                                          const __nv_bfloat16* Bh, const __nv_bfloat16* Bl,
                                          int m0, int j0, int n0, int tid) {
    uint32_t base = sb + buf * BUFSZ;
#pragma unroll
    for (int i = 0; i < 4; i++) {
        int v = tid + i * 256;          // 0..1023
        int row = v >> 3, ks = v & 7;
        uint32_t sw = SWZ128((uint32_t)(row * 128 + ks * 16));
        size_t goA = (size_t)(m0 + row) * NNODE + n0 + ks * 8;
        size_t goB = (size_t)(j0 + row) * NNODE + n0 + ks * 8;
        CP_ASYNC16(base + OFF_AH + sw, Ah + goA);
        CP_ASYNC16(base + OFF_AL + sw, Al + goA);
        CP_ASYNC16(base + OFF_BH + sw, Bh + goB);
        CP_ASYNC16(base + OFF_BL + sw, Bl + goB);
    }
}

// stage: diffusion order (0 -> x1, 1 -> x2); which: GCN index (0 -> adp1, 1 -> adp2)
__global__ void __launch_bounds__(256, 1) k_diff_mma(int stage, int which) {
    extern __shared__ __align__(1024) char smem[];
    const uint32_t sb = smem_u32(smem);
    const int tid = threadIdx.x, wid = tid >> 5, lane = tid & 31;
    const int z = blockIdx.z;
    const int m0 = blockIdx.y * 128;
    const int j0 = blockIdx.x * 128;
    const int aIdx = (z < 2) ? z : 2 + which;   // FIX: adp selected by GCN, not by order

    const __nv_bfloat16* __restrict__ Ah = g_ATh[aIdx];
    const __nv_bfloat16* __restrict__ Al = g_ATl[aIdx];
    const __nv_bfloat16* __restrict__ Bh = stage ? g_X1Th[z] : g_XTh;
    const __nv_bfloat16* __restrict__ Bl = stage ? g_X1Tl[z] : g_XTl;
    float* __restrict__ C = stage ? g_X2[z] : g_X1[z];

    const int warp_m = wid & 3;          // 4 warps along M (32 rows each)
    const int warp_n = wid >> 2;         // 2 warps along N (64 cols each)

    float acc[2][8][4];
#pragma unroll
    for (int mi = 0; mi < 2; mi++)
#pragma unroll
        for (int ni = 0; ni < 8; ni++)
#pragma unroll
            for (int q = 0; q < 4; q++) acc[mi][ni][q] = 0.f;

    diff_load(sb, 0, Ah, Al, Bh, Bl, m0, j0, 0, tid);
    CP_COMMIT();

    for (int kt = 0; kt < 8; kt++) {
        if (kt < 7) {
            diff_load(sb, (kt + 1) & 1, Ah, Al, Bh, Bl, m0, j0, (kt + 1) * 64, tid);
            CP_COMMIT();
            CP_WAIT(1);
        } else {
            CP_WAIT(0);
        }
        __syncthreads();

        const uint32_t base = sb + (kt & 1) * BUFSZ;
#pragma unroll
        for (int kk = 0; kk < 4; kk++) {           // 4 x k16 per BK=64
            uint32_t ah[2][4], al[2][4];
#pragma unroll
            for (int mi = 0; mi < 2; mi++) {
                uint32_t off = (uint32_t)((warp_m * 32 + mi * 16 + (lane & 15)) * 128
                                          + kk * 32 + (lane >> 4) * 16);
                uint32_t sw = SWZ128(off);
                ldsm_x4(ah[mi], base + OFF_AH + sw);
                ldsm_x4(al[mi], base + OFF_AL + sw);
            }
            uint32_t bh[8][2], bl[8][2];
#pragma unroll
            for (int ni = 0; ni < 8; ni++) {
                uint32_t off = (uint32_t)((warp_n * 64 + ni * 8 + (lane & 7)) * 128
                                          + kk * 32 + ((lane >> 3) & 1) * 16);
                uint32_t sw = SWZ128(off);
                ldsm_x2(bh[ni], base + OFF_BH + sw);
                ldsm_x2(bl[ni], base + OFF_BL + sw);
            }
#pragma unroll
            for (int mi = 0; mi < 2; mi++)
#pragma unroll
                for (int ni = 0; ni < 8; ni++) {
                    mma16816(acc[mi][ni], ah[mi], bh[ni]);
                    mma16816(acc[mi][ni], ah[mi], bl[ni]);
                    mma16816(acc[mi][ni], al[mi], bh[ni]);
                }
        }
        __syncthreads();
    }

    // epilogue
    const int g = lane >> 2, t = lane & 3;
#pragma unroll
    for (int mi = 0; mi < 2; mi++) {
        const int row = m0 + warp_m * 32 + mi * 16 + g;
#pragma unroll
        for (int ni = 0; ni < 8; ni++) {
            const int col = j0 + warp_n * 64 + ni * 8 + t * 2;
            *(float2*)(C + (size_t)row * BF + col) =
                make_float2(acc[mi][ni][0], acc[mi][ni][1]);
            *(float2*)(C + (size_t)(row + 8) * BF + col) =
                make_float2(acc[mi][ni][2], acc[mi][ni][3]);
        }
    }
}

// ---------------- output GEMM + fused epilogue (FFMA2) ----------------------
template <int BN, int ACT>
__global__ void __launch_bounds__(256)
k_out(const float* __restrict__ W, const float* __restrict__ bias,
      const float* __restrict__ state, float* __restrict__ outp) {
    constexpr int TN = BN / 16;
    constexpr int TN2 = TN / 2;
    __shared__ __align__(16) float Hs[128 * 33];
    __shared__ __align__(16) float Ws[33 * BN];

    const int tid = threadIdx.x;
    const int row0 = blockIdx.x * 128;
    const int tx = tid & 15, ty = tid >> 4;
    const int mm = ty * 8, cc0 = tx * TN;

    unsigned long long acc[8][TN2];
#pragma unroll
    for (int i = 0; i < 8; i++)
#pragma unroll
        for (int j = 0; j < TN2; j++) acc[i][j] = 0ULL;

    const float* chunks[7] = {g_X, g_X1[0], g_X2[0], g_X1[1], g_X2[1], g_X1[2], g_X2[2]};

    for (int kt = 0; kt < 14; kt++) {
        const int t = kt >> 1;
        const int fb = (kt & 1) * 33;
        const float* __restrict__ Hc = chunks[t];
        for (int i = tid; i < 128 * 33; i += 256) {
            int r = i / 33, f = i - r * 33;
            Hs[i] = Hc[(size_t)(row0 + r) * CIN_ + fb + f];
        }
        for (int i = tid; i < 33 * BN; i += 256) {
            int kk = i / BN, c = i - kk * BN;
            Ws[i] = W[(t * CIN_ + fb + kk) * BN + c];
        }
        __syncthreads();
#pragma unroll 3
        for (int kk = 0; kk < 33; kk++) {
            const unsigned long long* bp = (const unsigned long long*)&Ws[kk * BN + cc0];
            unsigned long long bv[TN2];
#pragma unroll
            for (int j = 0; j < TN2; j++) bv[j] = bp[j];
#pragma unroll
            for (int i = 0; i < 8; i++) {
                unsigned long long av = bcast2(Hs[(mm + i) * 33 + kk]);
#pragma unroll
                for (int j = 0; j < TN2; j++) ffma2(acc[i][j], av, bv[j]);
            }
        }
        __syncthreads();
    }

#pragma unroll
    for (int i = 0; i < 8; i++) {
        const int row = row0 + mm + i;
#pragma unroll
        for (int j = 0; j < TN2; j++) {
            float2 v = unpk2(acc[i][j]);
            const int c = cc0 + 2 * j;
            if (ACT == 0) {
                g_V[row * 128 + c]     = 1.f / (1.f + __expf(-(v.x + bias[c])));
                g_V[row * 128 + c + 1] = 1.f / (1.f + __expf(-(v.y + bias[c + 1])));
            } else {
                const int n = row >> 7, b = row & 127;
                float c0 = tanhf(v.x + bias[c]);
                float c1 = tanhf(v.y + bias[c + 1]);
                float u0 = g_V[row * 128 + 64 + c];
                float u1 = g_V[row * 128 + 64 + c + 1];
                const int si = (b * NNODE + n) * COUT_ + c;
                float st0 = state[si], st1 = state[si + 1];
                outp[si]     = u0 * st0 + (1.f - u0) * c0;
                outp[si + 1] = u1 * st1 + (1.f - u1) * c1;
            }
        }
    }
}

// ---------------- launch ----------------------------------------------------
extern "C" void kernel_launch(void* const* d_in, const int* in_sizes, int n_in,
                              void* d_out, int out_size) {
    const float* input = (const float*)d_in[0];
    const float* state = (const float*)d_in[1];
    const float* A0    = (const float*)d_in[2];
    const float* A1    = (const float*)d_in[3];
    const float* nv1_1 = (const float*)d_in[4];
    const float* nv2_1 = (const float*)d_in[5];
    const float* W1    = (const float*)d_in[6];
    const float* b1    = (const float*)d_in[7];
    const float* nv1_2 = (const float*)d_in[8];
    const float* nv2_2 = (const float*)d_in[9];
    const float* W2    = (const float*)d_in[10];
    const float* b2    = (const float*)d_in[11];
    float* outp = (float*)d_out;

    cudaFuncSetAttribute(k_diff_mma, cudaFuncAttributeMaxDynamicSharedMemorySize, DIFF_SMEM);

    const int packGrid = (NNODE * BF + 255) / 256;
    const dim3 gDiff(BF / 128, NNODE / 128, 3);        // (66, 4, 3)
    const dim3 gSplit1(BF / 32, NNODE / 32, 1);
    const dim3 gSplit3(BF / 32, NNODE / 32, 3);

    k_adp<<<dim3(NNODE, 2), 512>>>(nv1_1, nv2_1, nv1_2, nv2_2);
    k_prepA<<<dim3(16, 16, 4), 256>>>(A0, A1);

    // GCN 1 (which = 0 -> adp1 for BOTH diffusion orders)
    k_pack1<<<packGrid, 256>>>(input, state);
    k_split<<<gSplit1, 256>>>(0);
    k_diff_mma<<<gDiff, 256, DIFF_SMEM>>>(0, 0);
    k_split<<<gSplit3, 256>>>(1);
    k_diff_mma<<<gDiff, 256, DIFF_SMEM>>>(1, 0);
    k_out<128, 0><<<NNODE * BB / 128, 256>>>(W1, b1, state, nullptr);

    // GCN 2 (which = 1 -> adp2 for BOTH diffusion orders)
    k_pack2<<<packGrid, 256>>>(input, state);
    k_split<<<gSplit1, 256>>>(0);
    k_diff_mma<<<gDiff, 256, DIFF_SMEM>>>(0, 1);
    k_split<<<gSplit3, 256>>>(1);
    k_diff_mma<<<gDiff, 256, DIFF_SMEM>>>(1, 1);
    k_out<64, 1><<<NNODE * BB / 128, 256>>>(W2, b2, state, outp);
}

// round 8
// speedup vs baseline: 1.9701x; 1.2150x over previous
#include <cuda_runtime.h>
#include <cuda_bf16.h>
#include <cstdint>

#define BB     128
#define NNODE  512
#define FIN_   2
#define COUT_  64
#define CIN_   66
#define BF     8448     // BB * CIN_
#define KPAD   512      // padded concat-K (462 -> 512, zeros)

// ---------------- scratch (static device globals) ---------------------------
static __device__ float g_ADP[2][NNODE * NNODE];
static __device__ float g_X  [NNODE * BF];
static __device__ float g_X1 [3][NNODE * BF];
static __device__ float g_V  [NNODE * BB * 128];
static __device__ __align__(16) __nv_bfloat16 g_ATh[4][NNODE * NNODE];
static __device__ __align__(16) __nv_bfloat16 g_ATl[4][NNODE * NNODE];
static __device__ __align__(16) __nv_bfloat16 g_XTh[BF * NNODE];
static __device__ __align__(16) __nv_bfloat16 g_XTl[BF * NNODE];
static __device__ __align__(16) __nv_bfloat16 g_X1Th[3][BF * NNODE];
static __device__ __align__(16) __nv_bfloat16 g_X1Tl[3][BF * NNODE];
// pre-split concatenated H for the output GEMM: row = n*128+b, k = chunk*66+f
static __device__ __align__(16) __nv_bfloat16 g_Hh[(size_t)NNODE * BB * KPAD];
static __device__ __align__(16) __nv_bfloat16 g_Hl[(size_t)NNODE * BB * KPAD];
// transposed, padded, split weights: [n][KPAD]
static __device__ __align__(16) __nv_bfloat16 g_W1h[128 * KPAD];
static __device__ __align__(16) __nv_bfloat16 g_W1l[128 * KPAD];
static __device__ __align__(16) __nv_bfloat16 g_W2h[64 * KPAD];
static __device__ __align__(16) __nv_bfloat16 g_W2l[64 * KPAD];

// ---------------- PTX helpers -----------------------------------------------
__device__ __forceinline__ uint32_t smem_u32(const void* p) {
    uint32_t a;
    asm("{ .reg .u64 t; cvta.to.shared.u64 t, %1; cvt.u32.u64 %0, t; }" : "=r"(a) : "l"(p));
    return a;
}
#define SWZ128(off) ((off) ^ (((off) >> 3) & 0x70))

#define CP_ASYNC16(sm, gp) \
    asm volatile("cp.async.cg.shared.global [%0], [%1], 16;" :: "r"(sm), "l"(gp))
#define CP_COMMIT() asm volatile("cp.async.commit_group;" ::: "memory")
#define CP_WAIT(n)  asm volatile("cp.async.wait_group %0;" :: "n"(n) : "memory")

__device__ __forceinline__ void ldsm_x4(uint32_t* r, uint32_t addr) {
    asm volatile("ldmatrix.sync.aligned.m8n8.x4.shared.b16 {%0,%1,%2,%3}, [%4];"
                 : "=r"(r[0]), "=r"(r[1]), "=r"(r[2]), "=r"(r[3]) : "r"(addr));
}
__device__ __forceinline__ void ldsm_x2(uint32_t* r, uint32_t addr) {
    asm volatile("ldmatrix.sync.aligned.m8n8.x2.shared.b16 {%0,%1}, [%2];"
                 : "=r"(r[0]), "=r"(r[1]) : "r"(addr));
}
__device__ __forceinline__ void mma16816(float* c, const uint32_t* a, const uint32_t* b) {
    asm volatile("mma.sync.aligned.m16n8k16.row.col.f32.bf16.bf16.f32 "
                 "{%0,%1,%2,%3}, {%4,%5,%6,%7}, {%8,%9}, {%0,%1,%2,%3};"
                 : "+f"(c[0]), "+f"(c[1]), "+f"(c[2]), "+f"(c[3])
                 : "r"(a[0]), "r"(a[1]), "r"(a[2]), "r"(a[3]), "r"(b[0]), "r"(b[1]));
}

// ---------------- adaptive adjacency ----------------------------------------
__global__ void k_adp(const float* __restrict__ nv1a, const float* __restrict__ nv2a,
                      const float* __restrict__ nv1b, const float* __restrict__ nv2b) {
    const int which = blockIdx.y;
    const float* nv1 = which ? nv1b : nv1a;
    const float* nv2 = which ? nv2b : nv2a;
    const int n = blockIdx.x, m = threadIdx.x;
    float w[10];
#pragma unroll
    for (int t = 0; t < 10; t++) w[t] = nv1[n * 10 + t];
    float v = 0.f;
#pragma unroll
    for (int t = 0; t < 10; t++) v += w[t] * nv2[t * NNODE + m];
    v = fmaxf(v, 0.f);
    __shared__ float red[512];
    red[m] = v; __syncthreads();
    for (int s = 256; s > 0; s >>= 1) { if (m < s) red[m] = fmaxf(red[m], red[m + s]); __syncthreads(); }
    float mx = red[0]; __syncthreads();
    float e = __expf(v - mx);
    red[m] = e; __syncthreads();
    for (int s = 256; s > 0; s >>= 1) { if (m < s) red[m] += red[m + s]; __syncthreads(); }
    g_ADP[which][n * NNODE + m] = e / red[0];
}

// ---------------- A transpose + bf16 split ----------------------------------
__global__ void k_prepA(const float* __restrict__ A0, const float* __restrict__ A1) {
    const int a = blockIdx.z;
    const float* __restrict__ src = (a == 0) ? A0 : (a == 1) ? A1 : g_ADP[a - 2];
    __shared__ float t[32][33];
    const int mb = blockIdx.x * 32, nb = blockIdx.y * 32;
    const int tx = threadIdx.x & 31, ty = threadIdx.x >> 5;
#pragma unroll
    for (int r = 0; r < 32; r += 8)
        t[ty + r][tx] = src[(nb + ty + r) * NNODE + mb + tx];
    __syncthreads();
#pragma unroll
    for (int r = 0; r < 32; r += 8) {
        float v = t[tx][ty + r];
        __nv_bfloat16 h = __float2bfloat16(v);
        float rem = v - __bfloat162float(h);
        int o = (mb + ty + r) * NNODE + nb + tx;
        g_ATh[a][o] = h;
        g_ATl[a][o] = __float2bfloat16(rem);
    }
}

// ---------------- W transpose + pad + bf16 split ----------------------------
// z=0: W1 [462][128] -> g_W1h/l [128][512]; z=1: W2 [462][64] -> g_W2h/l
__global__ void k_prepW(const float* __restrict__ W1, const float* __restrict__ W2) {
    const int z = blockIdx.y;
    const int BN = z ? 64 : 128;
    const float* __restrict__ W = z ? W2 : W1;
    __nv_bfloat16* __restrict__ dh = z ? g_W2h : g_W1h;
    __nv_bfloat16* __restrict__ dl = z ? g_W2l : g_W1l;
    int idx = blockIdx.x * 256 + threadIdx.x;          // over KPAD*BN
    if (idx >= KPAD * BN) return;
    int k = idx / BN, n = idx - k * BN;
    float v = (k < 462) ? W[k * BN + n] : 0.f;
    __nv_bfloat16 h = __float2bfloat16(v);
    dh[n * KPAD + k] = h;
    dl[n * KPAD + k] = __float2bfloat16(v - __bfloat162float(h));
}

// ---------------- X transpose + bf16 split ----------------------------------
__global__ void k_split(int mode) {
    const int z = (mode == 0) ? -1 : (int)blockIdx.z;
    const float* __restrict__ src = (z < 0) ? g_X : g_X1[z];
    __nv_bfloat16* __restrict__ dh = (z < 0) ? g_XTh : g_X1Th[z];
    __nv_bfloat16* __restrict__ dl = (z < 0) ? g_XTl : g_X1Tl[z];
    __shared__ float t[32][33];
    const int jb = blockIdx.x * 32, nb = blockIdx.y * 32;
    const int tx = threadIdx.x & 31, ty = threadIdx.x >> 5;
#pragma unroll
    for (int r = 0; r < 32; r += 8)
        t[ty + r][tx] = src[(size_t)(nb + ty + r) * BF + jb + tx];
    __syncthreads();
#pragma unroll
    for (int r = 0; r < 32; r += 8) {
        float v = t[tx][ty + r];
        __nv_bfloat16 h = __float2bfloat16(v);
        float rem = v - __bfloat162float(h);
        size_t o = (size_t)(jb + ty + r) * NNODE + nb + tx;
        dh[o] = h;
        dl[o] = __float2bfloat16(rem);
    }
}

// ---------------- pack kernels (also write split H chunk 0) -----------------
__device__ __forceinline__ void h_write(int n, int b, int f, float v) {
    size_t o = ((size_t)n * BB + b) * KPAD + f;        // chunk 0: k = f
    __nv_bfloat16 h = __float2bfloat16(v);
    g_Hh[o] = h;
    g_Hl[o] = __float2bfloat16(v - __bfloat162float(h));
}
__global__ void k_pack1(const float* __restrict__ inp, const float* __restrict__ st) {
    int idx = blockIdx.x * 256 + threadIdx.x;
    if (idx >= NNODE * BF) return;
    int n = idx / BF, r = idx - n * BF;
    int b = r / CIN_, f = r - b * CIN_;
    float v = (f < FIN_) ? inp[(b * NNODE + n) * FIN_ + f]
                         : st[(b * NNODE + n) * COUT_ + (f - FIN_)];
    g_X[idx] = v;
    h_write(n, b, f, v);
}
__global__ void k_pack2(const float* __restrict__ inp, const float* __restrict__ st) {
    int idx = blockIdx.x * 256 + threadIdx.x;
    if (idx >= NNODE * BF) return;
    int n = idx / BF, r = idx - n * BF;
    int b = r / CIN_, f = r - b * CIN_;
    float v;
    if (f < FIN_) v = inp[(b * NNODE + n) * FIN_ + f];
    else {
        int c = f - FIN_;
        v = g_V[(n * BB + b) * 128 + c] * st[(b * NNODE + n) * COUT_ + c];
    }
    g_X[idx] = v;
    h_write(n, b, f, v);
}

// ---------------- diffusion GEMM on HMMA (split-bf16 x3) --------------------
#define OFF_AH 0
#define OFF_AL 16384
#define OFF_BH 32768
#define OFF_BL 49152
#define BUFSZ  65536
#define DIFF_SMEM (2 * BUFSZ)

__device__ __forceinline__ void diff_load(uint32_t sb, int buf,
                                          const __nv_bfloat16* Ah, const __nv_bfloat16* Al,
                                          const __nv_bfloat16* Bh, const __nv_bfloat16* Bl,
                                          int m0, int j0, int n0, int tid) {
    uint32_t base = sb + buf * BUFSZ;
#pragma unroll
    for (int i = 0; i < 4; i++) {
        int v = tid + i * 256;
        int row = v >> 3, ks = v & 7;
        uint32_t sw = SWZ128((uint32_t)(row * 128 + ks * 16));
        size_t goA = (size_t)(m0 + row) * NNODE + n0 + ks * 8;
        size_t goB = (size_t)(j0 + row) * NNODE + n0 + ks * 8;
        CP_ASYNC16(base + OFF_AH + sw, Ah + goA);
        CP_ASYNC16(base + OFF_AL + sw, Al + goA);
        CP_ASYNC16(base + OFF_BH + sw, Bh + goB);
        CP_ASYNC16(base + OFF_BL + sw, Bl + goB);
    }
}

// stage: diffusion order (0 -> x1, 1 -> x2); which: GCN index
__global__ void __launch_bounds__(256, 1) k_diff_mma(int stage, int which) {
    extern __shared__ __align__(1024) char smem[];
    const uint32_t sb = smem_u32(smem);
    const int tid = threadIdx.x, wid = tid >> 5, lane = tid & 31;
    const int z = blockIdx.z;
    const int m0 = blockIdx.y * 128;
    const int j0 = blockIdx.x * 128;
    const int aIdx = (z < 2) ? z : 2 + which;

    const __nv_bfloat16* __restrict__ Ah = g_ATh[aIdx];
    const __nv_bfloat16* __restrict__ Al = g_ATl[aIdx];
    const __nv_bfloat16* __restrict__ Bh = stage ? g_X1Th[z] : g_XTh;
    const __nv_bfloat16* __restrict__ Bl = stage ? g_X1Tl[z] : g_XTl;

    const int warp_m = wid & 3;
    const int warp_n = wid >> 2;

    float acc[2][8][4];
#pragma unroll
    for (int mi = 0; mi < 2; mi++)
#pragma unroll
        for (int ni = 0; ni < 8; ni++)
#pragma unroll
            for (int q = 0; q < 4; q++) acc[mi][ni][q] = 0.f;

    diff_load(sb, 0, Ah, Al, Bh, Bl, m0, j0, 0, tid);
    CP_COMMIT();

    for (int kt = 0; kt < 8; kt++) {
        if (kt < 7) {
            diff_load(sb, (kt + 1) & 1, Ah, Al, Bh, Bl, m0, j0, (kt + 1) * 64, tid);
            CP_COMMIT();
            CP_WAIT(1);
        } else {
            CP_WAIT(0);
        }
        __syncthreads();

        const uint32_t base = sb + (kt & 1) * BUFSZ;
#pragma unroll
        for (int kk = 0; kk < 4; kk++) {
            uint32_t ah[2][4], al[2][4];
#pragma unroll
            for (int mi = 0; mi < 2; mi++) {
                uint32_t off = (uint32_t)((warp_m * 32 + mi * 16 + (lane & 15)) * 128
                                          + kk * 32 + (lane >> 4) * 16);
                uint32_t sw = SWZ128(off);
                ldsm_x4(ah[mi], base + OFF_AH + sw);
                ldsm_x4(al[mi], base + OFF_AL + sw);
            }
            uint32_t bh[8][2], bl[8][2];
#pragma unroll
            for (int ni = 0; ni < 8; ni++) {
                uint32_t off = (uint32_t)((warp_n * 64 + ni * 8 + (lane & 7)) * 128
                                          + kk * 32 + ((lane >> 3) & 1) * 16);
                uint32_t sw = SWZ128(off);
                ldsm_x2(bh[ni], base + OFF_BH + sw);
                ldsm_x2(bl[ni], base + OFF_BL + sw);
            }
#pragma unroll
            for (int mi = 0; mi < 2; mi++)
#pragma unroll
                for (int ni = 0; ni < 8; ni++) {
                    mma16816(acc[mi][ni], ah[mi], bh[ni]);
                    mma16816(acc[mi][ni], ah[mi], bl[ni]);
                    mma16816(acc[mi][ni], al[mi], bh[ni]);
                }
        }
        __syncthreads();
    }

    // epilogue: write split H chunk (and g_X1 float for stage 0)
    const int ch = (stage ? 2 : 1) + 2 * z;
    const int g = lane >> 2, t = lane & 3;
    float* __restrict__ C1 = g_X1[z];
#pragma unroll
    for (int mi = 0; mi < 2; mi++) {
        const int row = m0 + warp_m * 32 + mi * 16 + g;
#pragma unroll
        for (int ni = 0; ni < 8; ni++) {
            const int col = j0 + warp_n * 64 + ni * 8 + t * 2;   // always even
            const int b = col / CIN_, f = col - b * CIN_;        // f even, f+1 <= 65
#pragma unroll
            for (int h2 = 0; h2 < 2; h2++) {
                const int rr = row + h2 * 8;
                const float vx = acc[mi][ni][h2 * 2 + 0];
                const float vy = acc[mi][ni][h2 * 2 + 1];
                if (stage == 0)
                    *(float2*)(C1 + (size_t)rr * BF + col) = make_float2(vx, vy);
                const size_t ho = ((size_t)rr * BB + b) * KPAD + ch * CIN_ + f;
                __nv_bfloat162 hh = __floats2bfloat162_rn(vx, vy);
                *(__nv_bfloat162*)(g_Hh + ho) = hh;
                float lx = vx - __bfloat162float(hh.x);
                float ly = vy - __bfloat162float(hh.y);
                *(__nv_bfloat162*)(g_Hl + ho) = __floats2bfloat162_rn(lx, ly);
            }
        }
    }
}

// ---------------- output GEMM on HMMA + fused epilogue ----------------------
// H[65536 x KPAD] @ WT^T -> [65536 x BN]; BM=128, BK=64, 8 k-tiles.
template <int BN, int ACT>
__global__ void __launch_bounds__(256, 1)
k_out_mma(const float* __restrict__ bias, const float* __restrict__ state,
          float* __restrict__ outp) {
    constexpr int NI = BN / 16;              // mma n8 tiles per warp_n
    constexpr int ASZ = 16384;               // 128 x 64 bf16
    constexpr int BSZ = BN * 64 * 2;         // BN x 64 bf16
    constexpr int OAH = 0, OAL = ASZ, OBH = 2 * ASZ, OBL = 2 * ASZ + BSZ;
    constexpr int KBUF = 2 * ASZ + 2 * BSZ;

    extern __shared__ __align__(1024) char smem[];
    const uint32_t sb = smem_u32(smem);
    const int tid = threadIdx.x, wid = tid >> 5, lane = tid & 31;
    const int row0 = blockIdx.x * 128;

    const __nv_bfloat16* __restrict__ Wh = (BN == 128) ? g_W1h : g_W2h;
    const __nv_bfloat16* __restrict__ Wl = (BN == 128) ? g_W1l : g_W2l;

    const int warp_m = wid & 3;
    const int warp_n = wid >> 2;

    float acc[2][NI][4];
#pragma unroll
    for (int mi = 0; mi < 2; mi++)
#pragma unroll
        for (int ni = 0; ni < NI; ni++)
#pragma unroll
            for (int q = 0; q < 4; q++) acc[mi][ni][q] = 0.f;

    auto load_tile = [&](int buf, int k0) {
        uint32_t base = sb + buf * KBUF;
#pragma unroll
        for (int i = 0; i < 4; i++) {        // A: 1024 16B chunks / 256 thr
            int v = tid + i * 256;
            int row = v >> 3, ks = v & 7;
            uint32_t sw = SWZ128((uint32_t)(row * 128 + ks * 16));
            size_t go = (size_t)(row0 + row) * KPAD + k0 + ks * 8;
            CP_ASYNC16(base + OAH + sw, g_Hh + go);
            CP_ASYNC16(base + OAL + sw, g_Hl + go);
        }
#pragma unroll
        for (int i = 0; i < BN * 8 / 256; i++) {   // B: BN*8 chunks
            int v = tid + i * 256;
            int row = v >> 3, ks = v & 7;
            uint32_t sw = SWZ128((uint32_t)(row * 128 + ks * 16));
            size_t go = (size_t)row * KPAD + k0 + ks * 8;
            CP_ASYNC16(base + OBH + sw, Wh + go);
            CP_ASYNC16(base + OBL + sw, Wl + go);
        }
    };

    load_tile(0, 0);
    CP_COMMIT();

    for (int kt = 0; kt < 8; kt++) {
        if (kt < 7) {
            load_tile((kt + 1) & 1, (kt + 1) * 64);
            CP_COMMIT();
            CP_WAIT(1);
        } else {
            CP_WAIT(0);
        }
        __syncthreads();

        const uint32_t base = sb + (kt & 1) * KBUF;
#pragma unroll
        for (int kk = 0; kk < 4; kk++) {
            uint32_t ah[2][4], al[2][4];
#pragma unroll
            for (int mi = 0; mi < 2; mi++) {
                uint32_t off = (uint32_t)((warp_m * 32 + mi * 16 + (lane & 15)) * 128
                                          + kk * 32 + (lane >> 4) * 16);
                uint32_t sw = SWZ128(off);
                ldsm_x4(ah[mi], base + OAH + sw);
                ldsm_x4(al[mi], base + OAL + sw);
            }
            uint32_t bh[NI][2], bl[NI][2];
#pragma unroll
            for (int ni = 0; ni < NI; ni++) {
                uint32_t off = (uint32_t)((warp_n * (BN / 2) + ni * 8 + (lane & 7)) * 128
                                          + kk * 32 + ((lane >> 3) & 1) * 16);
                uint32_t sw = SWZ128(off);
                ldsm_x2(bh[ni], base + OBH + sw);
                ldsm_x2(bl[ni], base + OBL + sw);
            }
#pragma unroll
            for (int mi = 0; mi < 2; mi++)
#pragma unroll
                for (int ni = 0; ni < NI; ni++) {
                    mma16816(acc[mi][ni], ah[mi], bh[ni]);
                    mma16816(acc[mi][ni], ah[mi], bl[ni]);
                    mma16816(acc[mi][ni], al[mi], bh[ni]);
                }
        }
        __syncthreads();
    }

    // fused epilogue
    const int g = lane >> 2, t = lane & 3;
#pragma unroll
    for (int mi = 0; mi < 2; mi++) {
        const int row = row0 + warp_m * 32 + mi * 16 + g;
#pragma unroll
        for (int ni = 0; ni < NI; ni++) {
            const int col = warp_n * (BN / 2) + ni * 8 + t * 2;   // even
            const float b0 = bias[col], b1 = bias[col + 1];
#pragma unroll
            for (int h2 = 0; h2 < 2; h2++) {
                const int rr = row + h2 * 8;
                const float vx = acc[mi][ni][h2 * 2 + 0] + b0;
                const float vy = acc[mi][ni][h2 * 2 + 1] + b1;
                if (ACT == 0) {
                    *(float2*)(g_V + (size_t)rr * 128 + col) =
                        make_float2(1.f / (1.f + __expf(-vx)),
                                    1.f / (1.f + __expf(-vy)));
                } else {
                    const int n = rr >> 7, b = rr & 127;
                    const float c0 = tanhf(vx), c1 = tanhf(vy);
                    const float u0 = g_V[(size_t)rr * 128 + 64 + col];
                    const float u1 = g_V[(size_t)rr * 128 + 64 + col + 1];
                    const size_t si = ((size_t)b * NNODE + n) * COUT_ + col;
                    const float st0 = state[si], st1 = state[si + 1];
                    *(float2*)(outp + si) =
                        make_float2(u0 * st0 + (1.f - u0) * c0,
                                    u1 * st1 + (1.f - u1) * c1);
                }
            }
        }
    }
}

// ---------------- launch ----------------------------------------------------
extern "C" void kernel_launch(void* const* d_in, const int* in_sizes, int n_in,
                              void* d_out, int out_size) {
    const float* input = (const float*)d_in[0];
    const float* state = (const float*)d_in[1];
    const float* A0    = (const float*)d_in[2];
    const float* A1    = (const float*)d_in[3];
    const float* nv1_1 = (const float*)d_in[4];
    const float* nv2_1 = (const float*)d_in[5];
    const float* W1    = (const float*)d_in[6];
    const float* b1    = (const float*)d_in[7];
    const float* nv1_2 = (const float*)d_in[8];
    const float* nv2_2 = (const float*)d_in[9];
    const float* W2    = (const float*)d_in[10];
    const float* b2    = (const float*)d_in[11];
    float* outp = (float*)d_out;

    constexpr int KO128_SMEM = 2 * (2 * 16384 + 2 * 16384);   // 131072
    constexpr int KO64_SMEM  = 2 * (2 * 16384 + 2 * 8192);    //  98304
    cudaFuncSetAttribute(k_diff_mma, cudaFuncAttributeMaxDynamicSharedMemorySize, DIFF_SMEM);
    cudaFuncSetAttribute(k_out_mma<128, 0>, cudaFuncAttributeMaxDynamicSharedMemorySize, KO128_SMEM);
    cudaFuncSetAttribute(k_out_mma<64, 1>,  cudaFuncAttributeMaxDynamicSharedMemorySize, KO64_SMEM);

    const int packGrid = (NNODE * BF + 255) / 256;
    const dim3 gDiff(BF / 128, NNODE / 128, 3);
    const dim3 gSplit1(BF / 32, NNODE / 32, 1);
    const dim3 gSplit3(BF / 32, NNODE / 32, 3);

    k_adp<<<dim3(NNODE, 2), 512>>>(nv1_1, nv2_1, nv1_2, nv2_2);
    k_prepA<<<dim3(16, 16, 4), 256>>>(A0, A1);
    k_prepW<<<dim3((KPAD * 128 + 255) / 256, 2), 256>>>(W1, W2);

    // GCN 1 (adp1 for both orders)
    k_pack1<<<packGrid, 256>>>(input, state);
    k_split<<<gSplit1, 256>>>(0);
    k_diff_mma<<<gDiff, 256, DIFF_SMEM>>>(0, 0);
    k_split<<<gSplit3, 256>>>(1);
    k_diff_mma<<<gDiff, 256, DIFF_SMEM>>>(1, 0);
    k_out_mma<128, 0><<<NNODE * BB / 128, 256, KO128_SMEM>>>(b1, state, nullptr);

    // GCN 2 (adp2 for both orders)
    k_pack2<<<packGrid, 256>>>(input, state);
    k_split<<<gSplit1, 256>>>(0);
    k_diff_mma<<<gDiff, 256, DIFF_SMEM>>>(0, 1);
    k_split<<<gSplit3, 256>>>(1);
    k_diff_mma<<<gDiff, 256, DIFF_SMEM>>>(1, 1);
    k_out_mma<64, 1><<<NNODE * BB / 128, 256, KO64_SMEM>>>(b2, state, outp);
}